// round 4
// baseline (speedup 1.0000x reference)
#include <cuda_runtime.h>

// Problem constants (fixed by the reference)
#define DD   41
#define HH   159
#define WW   159
#define CIN  32
#define COUT 64
#define NB   2
#define NPTS 150000          // B * N_PER_BATCH
#define DM   20              // (41-3)/2+1
#define HM   79              // (159-3)/2+1
#define WM   79
#define WSZ  (27 * CIN * COUT)               // 55296 floats per weight tensor
#define MIDSZ ((long)NB * DM * HM * WM * COUT) // 15,976,960 floats (63.9 MB)
#define OUTSZ ((long)NB * CIN * DD * HH * WW)  // 66,337,344 floats

// Scratch: dense mid-grid accumulator (device global — no allocation allowed)
__device__ float g_mid[NB * DM * HM * WM * COUT];

// ---------------------------------------------------------------------------
// Kernel 0: zero d_out and g_mid (float4 grid-stride)
// ---------------------------------------------------------------------------
__global__ void zero_kernel(float4* __restrict__ out) {
    const long n_out4 = OUTSZ / 4;
    const long n_mid4 = MIDSZ / 4;
    const long total  = n_out4 + n_mid4;
    float4* mid4 = reinterpret_cast<float4*>(g_mid);
    const float4 z = make_float4(0.f, 0.f, 0.f, 0.f);
    for (long i = blockIdx.x * (long)blockDim.x + threadIdx.x; i < total;
         i += (long)gridDim.x * blockDim.x) {
        if (i < n_out4) out[i] = z;
        else            mid4[i - n_out4] = z;
    }
}

// Per-dim tap enumeration: mid coord m with 2m + k = c, k in {0,1,2}, 0<=m<Md.
// Odd c -> exactly one tap (k=1, always in range for this problem's dims).
// Even c -> k=0 (m=c/2) and/or k=2 (m=c/2-1), range-checked.
__device__ __forceinline__ int taps1d(int c, int Md, int* k, int* m) {
    if (c & 1) { k[0] = 1; m[0] = (c - 1) >> 1; return 1; }
    int h = c >> 1, n = 0;
    if (h < Md) { k[n] = 0; m[n] = h;     n++; }
    if (h > 0)  { k[n] = 2; m[n] = h - 1; n++; }
    return n;
}

// ---------------------------------------------------------------------------
// Phase 1: scatter conv.  One warp per point. w1 in smem [tap][ci][co].
// Lane handles co = {2*lane, 2*lane+1} via float2 smem loads.
// mid[m, co] += sum_ci f[ci] * w1[k, ci, co]   (atomic, fire-and-forget RED)
// ---------------------------------------------------------------------------
__global__ void __launch_bounds__(512, 1) scatter_conv(
    const float* __restrict__ feats,
    const int*   __restrict__ coors,
    const float* __restrict__ w1) {
    extern __shared__ float sh[];
    float* ws  = sh;            // WSZ floats
    float* fst = sh + WSZ;      // 16 warps * 32 floats staging

    for (int i = threadIdx.x; i < WSZ; i += blockDim.x) ws[i] = w1[i];
    __syncthreads();

    const int warp = threadIdx.x >> 5;
    const int lane = threadIdx.x & 31;
    float* fs = fst + warp * CIN;

    const int gw     = blockIdx.x * 16 + warp;
    const int stride = gridDim.x * 16;

    for (int n = gw; n < NPTS; n += stride) {
        const int4 c = reinterpret_cast<const int4*>(coors)[n]; // b,z,y,x
        __syncwarp();
        fs[lane] = feats[n * CIN + lane];
        __syncwarp();

        int kz[2], mz[2], ky[2], my[2], kx[2], mx[2];
        const int nz = taps1d(c.y, DM, kz, mz);
        const int ny = taps1d(c.z, HM, ky, my);
        const int nx = taps1d(c.w, WM, kx, mx);

        for (int iz = 0; iz < nz; iz++)
        for (int iy = 0; iy < ny; iy++)
        for (int ix = 0; ix < nx; ix++) {
            const float2* wt2 = reinterpret_cast<const float2*>(
                ws + ((kz[iz] * 3 + ky[iy]) * 3 + kx[ix]) * (CIN * COUT));
            float ax = 0.f, ay = 0.f;
            const float4* f4p = reinterpret_cast<const float4*>(fs);
            #pragma unroll
            for (int j = 0; j < CIN / 4; j++) {
                const float4 f4 = f4p[j];
                float2 w;
                w = wt2[(4 * j + 0) * 32 + lane]; ax += f4.x * w.x; ay += f4.x * w.y;
                w = wt2[(4 * j + 1) * 32 + lane]; ax += f4.y * w.x; ay += f4.y * w.y;
                w = wt2[(4 * j + 2) * 32 + lane]; ax += f4.z * w.x; ay += f4.z * w.y;
                w = wt2[(4 * j + 3) * 32 + lane]; ax += f4.w * w.x; ay += f4.w * w.y;
            }
            const int mb = (((c.x * DM + mz[iz]) * HM + my[iy]) * WM + mx[ix]) * COUT;
            atomicAdd(&g_mid[mb + 2 * lane],     ax);
            atomicAdd(&g_mid[mb + 2 * lane + 1], ay);
        }
    }
}

// ---------------------------------------------------------------------------
// Phase 3: gather transposed-conv at the sparse points only.
// One warp per point; lane = output channel ci.
// w2 staged in smem TRANSPOSED to [tap][co][ci] for conflict-free reads.
// out[b, ci, z, y, x] = sum_taps sum_co mid[m, co] * w2[k, ci, co]
// ---------------------------------------------------------------------------
__global__ void __launch_bounds__(512, 1) gather_deconv(
    const int*   __restrict__ coors,
    const float* __restrict__ w2,
    float*       __restrict__ out) {
    extern __shared__ float sh[];
    float* ws  = sh;            // WSZ floats, transposed
    float* mst = sh + WSZ;      // 16 warps * 64 floats staging

    for (int i = threadIdx.x; i < WSZ; i += blockDim.x) {
        const int tap = i / (CIN * COUT);
        const int r   = i - tap * (CIN * COUT);
        const int ci  = r / COUT;
        const int co  = r - ci * COUT;
        ws[tap * (CIN * COUT) + co * CIN + ci] = w2[i];
    }
    __syncthreads();

    const int warp = threadIdx.x >> 5;
    const int lane = threadIdx.x & 31;
    float* ms = mst + warp * COUT;

    const int gw     = blockIdx.x * 16 + warp;
    const int stride = gridDim.x * 16;

    for (int n = gw; n < NPTS; n += stride) {
        const int4 c = reinterpret_cast<const int4*>(coors)[n]; // b,z,y,x

        int kz[2], mz[2], ky[2], my[2], kx[2], mx[2];
        const int nz = taps1d(c.y, DM, kz, mz);
        const int ny = taps1d(c.z, HM, ky, my);
        const int nx = taps1d(c.w, WM, kx, mx);

        float acc0 = 0.f, acc1 = 0.f;
        for (int iz = 0; iz < nz; iz++)
        for (int iy = 0; iy < ny; iy++)
        for (int ix = 0; ix < nx; ix++) {
            const int mb = (((c.x * DM + mz[iz]) * HM + my[iy]) * WM + mx[ix]) * COUT;
            __syncwarp();
            ms[lane]      = g_mid[mb + lane];
            ms[32 + lane] = g_mid[mb + 32 + lane];
            __syncwarp();

            const float* wt = ws + ((kz[iz] * 3 + ky[iy]) * 3 + kx[ix]) * (CIN * COUT);
            const float4* m4 = reinterpret_cast<const float4*>(ms);
            #pragma unroll
            for (int j = 0; j < COUT / 4; j++) {
                const float4 mv = m4[j];
                acc0 += mv.x * wt[(4 * j + 0) * CIN + lane];
                acc1 += mv.y * wt[(4 * j + 1) * CIN + lane];
                acc0 += mv.z * wt[(4 * j + 2) * CIN + lane];
                acc1 += mv.w * wt[(4 * j + 3) * CIN + lane];
            }
        }
        long o = (long)(c.x * CIN + lane) * DD + c.y;
        o = o * HH + c.z;
        o = o * WW + c.w;
        out[o] = acc0 + acc1;
    }
}

// ---------------------------------------------------------------------------
// Launcher (graph-capturable: kernel launches only; attribute/get calls are
// immediate, non-stream APIs)
// ---------------------------------------------------------------------------
extern "C" void kernel_launch(void* const* d_in, const int* in_sizes, int n_in,
                              void* d_out, int /*out_size*/) {
    const float* feats = nullptr;
    const int*   coors = nullptr;
    const float* w1 = nullptr;
    const float* w2 = nullptr;
    for (int i = 0; i < n_in; i++) {
        if      (in_sizes[i] == NPTS * CIN) feats = (const float*)d_in[i];
        else if (in_sizes[i] == NPTS * 4)   coors = (const int*)d_in[i];
        else if (in_sizes[i] == WSZ) {
            if (!w1) w1 = (const float*)d_in[i];
            else     w2 = (const float*)d_in[i];
        }
    }
    if (!feats || !coors || !w1 || !w2) return;

    int nsm = 148;
    cudaDeviceGetAttribute(&nsm, cudaDevAttrMultiProcessorCount, 0);

    const int smem1 = WSZ * 4 + 16 * CIN * 4;   // 223,232 B
    const int smem3 = WSZ * 4 + 16 * COUT * 4;  // 225,280 B
    cudaFuncSetAttribute(scatter_conv,  cudaFuncAttributeMaxDynamicSharedMemorySize, smem1);
    cudaFuncSetAttribute(gather_deconv, cudaFuncAttributeMaxDynamicSharedMemorySize, smem3);

    zero_kernel<<<2048, 256>>>(reinterpret_cast<float4*>(d_out));
    scatter_conv<<<nsm, 512, smem1>>>(feats, coors, w1);
    gather_deconv<<<nsm, 512, smem3>>>(coors, w2, reinterpret_cast<float*>(d_out));
}

// round 5
// speedup vs baseline: 1.1934x; 1.1934x over previous
#include <cuda_runtime.h>

// Problem constants (fixed by the reference)
#define DD   41
#define HH   159
#define WW   159
#define CIN  32
#define COUT 64
#define NB   2
#define NPTS 150000          // B * N_PER_BATCH
#define DM   20              // (41-3)/2+1
#define HM   79
#define WM   79
#define WSZ  (27 * CIN * COUT)                  // 55296 floats per weight tensor
#define MIDSZ (NB * DM * HM * WM * COUT)        // 15,976,960 floats
#define OUTSZ ((long)NB * CIN * DD * HH * WW)   // 66,337,344 floats

// Scratch (device globals — no allocation allowed)
__device__ alignas(16) float g_mid[MIDSZ];
__device__ int g_order[NPTS];
__device__ int g_cnt[8];
__device__ int g_cursor[8];
__device__ int g_bstart[8];
__device__ int g_gstart[9];

// ---------------------------------------------------------------------------
// Kernel 0: zero d_out, g_mid, g_cnt
// ---------------------------------------------------------------------------
__global__ void zero_kernel(float4* __restrict__ out) {
    const long n_out4 = OUTSZ / 4;
    const long n_mid4 = MIDSZ / 4;
    const long total  = n_out4 + n_mid4;
    float4* mid4 = reinterpret_cast<float4*>(g_mid);
    const float4 z = make_float4(0.f, 0.f, 0.f, 0.f);
    for (long i = blockIdx.x * (long)blockDim.x + threadIdx.x; i < total;
         i += (long)gridDim.x * blockDim.x) {
        if (i < n_out4) out[i] = z;
        else            mid4[i - n_out4] = z;
    }
    if (blockIdx.x == 0 && threadIdx.x < 8) g_cnt[threadIdx.x] = 0;
}

__device__ __forceinline__ int parity_cls(int4 c) {
    return ((c.y & 1) << 2) | ((c.z & 1) << 1) | (c.w & 1);
}

// ---------------------------------------------------------------------------
// Preprocessing: histogram -> scan -> scatter point indices into 8 parity buckets
// ---------------------------------------------------------------------------
__global__ void hist_kernel(const int* __restrict__ coors) {
    __shared__ int h[8];
    if (threadIdx.x < 8) h[threadIdx.x] = 0;
    __syncthreads();
    const int4* c4 = reinterpret_cast<const int4*>(coors);
    for (int n = blockIdx.x * blockDim.x + threadIdx.x; n < NPTS;
         n += gridDim.x * blockDim.x)
        atomicAdd(&h[parity_cls(c4[n])], 1);
    __syncthreads();
    if (threadIdx.x < 8 && h[threadIdx.x]) atomicAdd(&g_cnt[threadIdx.x], h[threadIdx.x]);
}

__global__ void scan_kernel() {
    int s = 0, gs = 0;
    for (int b = 0; b < 8; b++) {
        g_bstart[b] = s;
        g_cursor[b] = s;
        g_gstart[b] = gs;
        s  += g_cnt[b];
        gs += (g_cnt[b] + 3) >> 2;
    }
    g_gstart[8] = gs;
}

__global__ void scatter_idx_kernel(const int* __restrict__ coors) {
    int n = blockIdx.x * blockDim.x + threadIdx.x;
    if (n >= NPTS) return;
    const int cls  = parity_cls(reinterpret_cast<const int4*>(coors)[n]);
    const int lane = threadIdx.x & 31;
    unsigned mm = __match_any_sync(__activemask(), cls);
    int leader = __ffs(mm) - 1;
    int rank   = __popc(mm & ((1u << lane) - 1));
    int base;
    if (lane == leader) base = atomicAdd(&g_cursor[cls], __popc(mm));
    base = __shfl_sync(mm, base, leader);
    g_order[base + rank] = n;
}

// mid coord + validity for tap slot i (i=0 -> k=0 (or k=1 if odd), i=1 -> k=2)
__device__ __forceinline__ void midc(int c, int odd, int i, int Md, int& m, bool& v) {
    m = (c >> 1) - i;
    v = odd ? true : (i ? (c > 0) : (m < Md));
}

// ---------------------------------------------------------------------------
// Phase 1: scatter conv, 4 same-parity points per warp.
// lane = (half h, co-quad q): half h handles points {h, h+2}, co = 4q..4q+3.
// Weight in smem, layout [tap][ci][co] read as float4. Vector atomics to g_mid.
// ---------------------------------------------------------------------------
__global__ void __launch_bounds__(512, 1) scatter_conv(
    const float* __restrict__ feats,
    const int*   __restrict__ coors,
    const float* __restrict__ w1) {
    extern __shared__ float sh[];
    float4* ws4 = reinterpret_cast<float4*>(sh);   // WSZ floats
    float*  fst = sh + WSZ;                        // 16 warps * 128 floats

    for (int i = threadIdx.x; i < WSZ / 4; i += blockDim.x)
        ws4[i] = reinterpret_cast<const float4*>(w1)[i];
    __syncthreads();

    const int warp = threadIdx.x >> 5;
    const int lane = threadIdx.x & 31;
    const int h = lane >> 4;     // point-pair half
    const int q = lane & 15;     // co quad
    float* fsm = fst + warp * 128;
    const float4* fsm4 = reinterpret_cast<const float4*>(fsm);
    const int4* c4 = reinterpret_cast<const int4*>(coors);

    const int ngroups = g_gstart[8];
    for (int g = blockIdx.x * 16 + warp; g < ngroups; g += gridDim.x * 16) {
        int b = 0;
        #pragma unroll
        for (int i = 1; i < 8; i++) if (g >= g_gstart[i]) b = i;
        const int base = g_bstart[b] + (g - g_gstart[b]) * 4;
        const int cnt  = min(4, g_bstart[b] + g_cnt[b] - base);

        int4 pc[4];
        const int idx0 = g_order[base];
        __syncwarp();
        #pragma unroll
        for (int j = 0; j < 4; j++) {
            const int id = (j < cnt) ? g_order[base + j] : idx0;
            pc[j] = __ldg(c4 + id);
            fsm[j * 32 + lane] = (j < cnt) ? feats[id * CIN + lane] : 0.f;
        }
        __syncwarp();

        const int zo = pc[0].y & 1, yo = pc[0].z & 1, xo = pc[0].w & 1;
        const int nz = zo ? 1 : 2, ny = yo ? 1 : 2, nx = xo ? 1 : 2;

        for (int iz = 0; iz < nz; iz++)
        for (int iy = 0; iy < ny; iy++)
        for (int ix = 0; ix < nx; ix++) {
            const int kz = zo ? 1 : (iz ? 2 : 0);
            const int ky = yo ? 1 : (iy ? 2 : 0);
            const int kx = xo ? 1 : (ix ? 2 : 0);
            const float4* wt = ws4 + ((kz * 3 + ky) * 3 + kx) * (CIN * 16);

            float4 aA = make_float4(0.f, 0.f, 0.f, 0.f);
            float4 aB = make_float4(0.f, 0.f, 0.f, 0.f);
            #pragma unroll
            for (int jb = 0; jb < 8; jb++) {
                const float4 fA = fsm4[h * 8 + jb];
                const float4 fB = fsm4[(h + 2) * 8 + jb];
                const float4* wj = wt + (4 * jb) * 16 + q;
                float4 w;
                w = wj[0];
                aA.x += fA.x * w.x; aA.y += fA.x * w.y; aA.z += fA.x * w.z; aA.w += fA.x * w.w;
                aB.x += fB.x * w.x; aB.y += fB.x * w.y; aB.z += fB.x * w.z; aB.w += fB.x * w.w;
                w = wj[16];
                aA.x += fA.y * w.x; aA.y += fA.y * w.y; aA.z += fA.y * w.z; aA.w += fA.y * w.w;
                aB.x += fB.y * w.x; aB.y += fB.y * w.y; aB.z += fB.y * w.z; aB.w += fB.y * w.w;
                w = wj[32];
                aA.x += fA.z * w.x; aA.y += fA.z * w.y; aA.z += fA.z * w.z; aA.w += fA.z * w.w;
                aB.x += fB.z * w.x; aB.y += fB.z * w.y; aB.z += fB.z * w.z; aB.w += fB.z * w.w;
                w = wj[48];
                aA.x += fA.w * w.x; aA.y += fA.w * w.y; aA.z += fA.w * w.z; aA.w += fA.w * w.w;
                aB.x += fB.w * w.x; aB.y += fB.w * w.y; aB.z += fB.w * w.z; aB.w += fB.w * w.w;
            }

            #pragma unroll
            for (int pp = 0; pp < 2; pp++) {
                const int4 c = pc[h + 2 * pp];
                const float4 a = pp ? aB : aA;
                int mz, my, mx; bool vz, vy, vx;
                midc(c.y, zo, iz, DM, mz, vz);
                midc(c.z, yo, iy, HM, my, vy);
                midc(c.w, xo, ix, WM, mx, vx);
                if (vz && vy && vx) {
                    float* p = g_mid + ((((c.x * DM + mz) * HM + my) * WM + mx) << 6) + 4 * q;
                    asm volatile("red.global.add.v4.f32 [%0], {%1,%2,%3,%4};"
                                 :: "l"(p), "f"(a.x), "f"(a.y), "f"(a.z), "f"(a.w)
                                 : "memory");
                }
            }
        }
    }
}

// ---------------------------------------------------------------------------
// Phase 3: gather transposed-conv, 4 same-parity points per warp. lane = ci.
// Weights in smem packed as float4 [tap][co/4][ci] (4 co per float4).
// Mid rows staged per tap in smem, read via broadcast float4.
// ---------------------------------------------------------------------------
__global__ void __launch_bounds__(352, 1) gather_deconv(
    const int*   __restrict__ coors,
    const float* __restrict__ w2,
    float*       __restrict__ out) {
    extern __shared__ float sh[];
    float4* wst4 = reinterpret_cast<float4*>(sh);  // 27*16*32 float4 = WSZ floats
    float*  mst  = sh + WSZ;                       // 11 warps * 256 floats

    const float4* w2_4 = reinterpret_cast<const float4*>(w2);
    for (int i = threadIdx.x; i < 27 * 512; i += blockDim.x) {
        const int tap = i >> 9, r = i & 511, cog = r >> 5, ci = r & 31;
        wst4[(tap * 16 + cog) * 32 + ci] = w2_4[(tap * 32 + ci) * 16 + cog];
    }
    __syncthreads();

    const int warp = threadIdx.x >> 5;
    const int lane = threadIdx.x & 31;
    float* msm = mst + warp * 256;
    const float4* msm4 = reinterpret_cast<const float4*>(msm);
    const int4* c4 = reinterpret_cast<const int4*>(coors);

    const int ngroups = g_gstart[8];
    for (int g = blockIdx.x * 11 + warp; g < ngroups; g += gridDim.x * 11) {
        int b = 0;
        #pragma unroll
        for (int i = 1; i < 8; i++) if (g >= g_gstart[i]) b = i;
        const int base = g_bstart[b] + (g - g_gstart[b]) * 4;
        const int cnt  = min(4, g_bstart[b] + g_cnt[b] - base);

        int4 pc[4];
        const int idx0 = g_order[base];
        #pragma unroll
        for (int j = 0; j < 4; j++)
            pc[j] = __ldg(c4 + ((j < cnt) ? g_order[base + j] : idx0));

        const int zo = pc[0].y & 1, yo = pc[0].z & 1, xo = pc[0].w & 1;
        const int nz = zo ? 1 : 2, ny = yo ? 1 : 2, nx = xo ? 1 : 2;

        float acc[4] = {0.f, 0.f, 0.f, 0.f};
        for (int iz = 0; iz < nz; iz++)
        for (int iy = 0; iy < ny; iy++)
        for (int ix = 0; ix < nx; ix++) {
            const int kz = zo ? 1 : (iz ? 2 : 0);
            const int ky = yo ? 1 : (iy ? 2 : 0);
            const int kx = xo ? 1 : (ix ? 2 : 0);

            __syncwarp();
            #pragma unroll
            for (int j = 0; j < 4; j++) {
                const int4 c = pc[j];
                int mz, my, mx; bool vz, vy, vx;
                midc(c.y, zo, iz, DM, mz, vz);
                midc(c.z, yo, iy, HM, my, vy);
                midc(c.w, xo, ix, WM, mx, vx);
                const bool v = vz && vy && vx;
                const int mb = v ? ((((c.x * DM + mz) * HM + my) * WM + mx) << 6) : 0;
                msm[j * 64 + lane]      = v ? g_mid[mb + lane]      : 0.f;
                msm[j * 64 + 32 + lane] = v ? g_mid[mb + 32 + lane] : 0.f;
            }
            __syncwarp();

            const float4* wt = wst4 + ((kz * 3 + ky) * 3 + kx) * 512;
            #pragma unroll
            for (int cog = 0; cog < 16; cog++) {
                const float4 w = wt[cog * 32 + lane];
                #pragma unroll
                for (int j = 0; j < 4; j++) {
                    const float4 m = msm4[j * 16 + cog];
                    acc[j] += m.x * w.x + m.y * w.y + m.z * w.z + m.w * w.w;
                }
            }
        }

        for (int j = 0; j < cnt; j++) {
            const int4 c = pc[j];
            long o = (long)(c.x * CIN + lane) * DD + c.y;
            o = o * HH + c.z;
            o = o * WW + c.w;
            out[o] = acc[j];
        }
    }
}

// ---------------------------------------------------------------------------
// Launcher
// ---------------------------------------------------------------------------
extern "C" void kernel_launch(void* const* d_in, const int* in_sizes, int n_in,
                              void* d_out, int /*out_size*/) {
    const float* feats = nullptr;
    const int*   coors = nullptr;
    const float* w1 = nullptr;
    const float* w2 = nullptr;
    for (int i = 0; i < n_in; i++) {
        if      (in_sizes[i] == NPTS * CIN) feats = (const float*)d_in[i];
        else if (in_sizes[i] == NPTS * 4)   coors = (const int*)d_in[i];
        else if (in_sizes[i] == WSZ) {
            if (!w1) w1 = (const float*)d_in[i];
            else     w2 = (const float*)d_in[i];
        }
    }
    if (!feats || !coors || !w1 || !w2) return;

    int nsm = 148;
    cudaDeviceGetAttribute(&nsm, cudaDevAttrMultiProcessorCount, 0);

    const int smem1 = WSZ * 4 + 16 * 128 * 4;   // 229,376 B
    const int smem3 = WSZ * 4 + 11 * 256 * 4;   // 232,448 B
    cudaFuncSetAttribute(scatter_conv,  cudaFuncAttributeMaxDynamicSharedMemorySize, smem1);
    cudaFuncSetAttribute(gather_deconv, cudaFuncAttributeMaxDynamicSharedMemorySize, smem3);

    zero_kernel<<<2048, 256>>>(reinterpret_cast<float4*>(d_out));
    hist_kernel<<<512, 256>>>(coors);
    scan_kernel<<<1, 1>>>();
    scatter_idx_kernel<<<(NPTS + 255) / 256, 256>>>(coors);
    scatter_conv<<<nsm, 512, smem1>>>(feats, coors, w1);
    gather_deconv<<<nsm, 352, smem3>>>(coors, w2, reinterpret_cast<float*>(d_out));
}

// round 6
// speedup vs baseline: 1.3355x; 1.1190x over previous
#include <cuda_runtime.h>

// Problem constants (fixed by the reference)
#define DD   41
#define HH   159
#define WW   159
#define CIN  32
#define COUT 64
#define NB   2
#define NPTS 150000
#define DM   20
#define HM   79
#define WM   79
#define WSZ  (27 * CIN * COUT)                  // 55296 floats per weight tensor
#define MIDSZ (NB * DM * HM * WM * COUT)        // 15,976,960 floats
#define OUTSZ ((long)NB * CIN * DD * HH * WW)   // 66,337,344 floats

#define NW 16     // warps per CTA
#define GP 8      // points per group (all same parity class)

// Scratch (device globals — zero-initialized at load; counters self-reset per replay)
__device__ alignas(16) float g_mid[MIDSZ];
__device__ int g_order[NPTS];
__device__ int g_cnt[8];      // live histogram (reset by scan for next replay)
__device__ int g_cntS[8];     // stable copy used by conv kernels
__device__ int g_bstart[8];
__device__ int g_ng[8];       // groups of GP per class
__device__ int g_cursor[8];   // scatter_idx cursors
__device__ int g_ccur1[8];    // scatter_conv chunk cursors
__device__ int g_ccur2[8];    // gather_deconv chunk cursors

// Packed fp32x2 FMA (sm_103a FFMA2 — PTX-only path, 2x fp32 rate)
__device__ __forceinline__ void ffma2(unsigned long long& d,
                                      unsigned long long a,
                                      unsigned long long b) {
    asm("fma.rn.f32x2 %0, %1, %2, %0;" : "+l"(d) : "l"(a), "l"(b));
}

// ---------------------------------------------------------------------------
// Kernel 0: zero d_out + g_mid, and build the parity histogram (fused)
// ---------------------------------------------------------------------------
__global__ void zero_hist(float4* __restrict__ out, const int* __restrict__ coors) {
    __shared__ int h[8];
    if (threadIdx.x < 8) h[threadIdx.x] = 0;
    __syncthreads();

    const long n_out4 = OUTSZ / 4;
    const long n_mid4 = MIDSZ / 4;
    const long total  = n_out4 + n_mid4;
    float4* mid4 = reinterpret_cast<float4*>(g_mid);
    const float4 z = make_float4(0.f, 0.f, 0.f, 0.f);
    const long gstride = (long)gridDim.x * blockDim.x;
    for (long i = blockIdx.x * (long)blockDim.x + threadIdx.x; i < total; i += gstride) {
        if (i < n_out4) out[i] = z;
        else            mid4[i - n_out4] = z;
    }

    const int4* c4 = reinterpret_cast<const int4*>(coors);
    for (int n = blockIdx.x * blockDim.x + threadIdx.x; n < NPTS; n += (int)gstride) {
        const int4 c = c4[n];
        atomicAdd(&h[((c.y & 1) << 2) | ((c.z & 1) << 1) | (c.w & 1)], 1);
    }
    __syncthreads();
    if (threadIdx.x < 8 && h[threadIdx.x]) atomicAdd(&g_cnt[threadIdx.x], h[threadIdx.x]);
}

// ---------------------------------------------------------------------------
// Scan: prefix sums, cursors, and counter self-reset for graph replay
// ---------------------------------------------------------------------------
__global__ void scan_kernel() {
    int s = 0;
    for (int b = 0; b < 8; b++) {
        const int c = g_cnt[b];
        g_cntS[b]   = c;
        g_bstart[b] = s;
        g_cursor[b] = s;
        g_ng[b]     = (c + GP - 1) / GP;
        g_ccur1[b]  = 0;
        g_ccur2[b]  = 0;
        g_cnt[b]    = 0;      // reset for next replay
        s += c;
    }
}

__global__ void scatter_idx_kernel(const int* __restrict__ coors) {
    const int n = blockIdx.x * blockDim.x + threadIdx.x;
    if (n >= NPTS) return;
    const int4 c  = reinterpret_cast<const int4*>(coors)[n];
    const int cls = ((c.y & 1) << 2) | ((c.z & 1) << 1) | (c.w & 1);
    const int lane = threadIdx.x & 31;
    unsigned mm = __match_any_sync(__activemask(), cls);
    int leader = __ffs(mm) - 1;
    int rank   = __popc(mm & ((1u << lane) - 1));
    int base;
    if (lane == leader) base = atomicAdd(&g_cursor[cls], __popc(mm));
    base = __shfl_sync(mm, base, leader);
    g_order[base + rank] = n;
}

// ---------------------------------------------------------------------------
// Phase 1: scatter conv. Persistent CTAs, class-major chunk scheduling.
// Per class only its <=8 taps live in smem (64KB) -> 2 CTAs/SM.
// Warp handles GP=8 same-parity points; lane = (half h, co-quad q);
// lane's points = {h, h+2, h+4, h+6}. FFMA2 packed accumulation.
// ---------------------------------------------------------------------------
__global__ void __launch_bounds__(512, 2) scatter_conv(
    const float* __restrict__ feats,
    const int*   __restrict__ coors,
    const float* __restrict__ w1) {
    extern __shared__ float sh[];
    float4* ws4 = reinterpret_cast<float4*>(sh);                       // 8*512 float4
    unsigned long long* fd = reinterpret_cast<unsigned long long*>(sh + 16384); // NW*GP*32 ull
    int4* sco = reinterpret_cast<int4*>(fd + NW * GP * 32);            // NW*GP int4
    __shared__ int s_chunk;

    const int tid  = threadIdx.x;
    const int warp = tid >> 5, lane = tid & 31;
    const int h = lane >> 4, q = lane & 15;
    unsigned long long* fdw = fd + warp * (GP * 32);
    int4* scow = sco + warp * GP;
    const int4* c4 = reinterpret_cast<const int4*>(coors);

    int loaded = -1;
    for (int b = 0; b < 8; b++) {
        const int zo = (b >> 2) & 1, yo = (b >> 1) & 1, xo = b & 1;
        const int nx = 2 - xo, ny = 2 - yo, nz = 2 - zo;
        const int ntap = nx * ny * nz;
        const int ng = g_ng[b];
        const int bs = g_bstart[b], bc = g_cntS[b];
        while (true) {
            __syncthreads();
            if (tid == 0) s_chunk = atomicAdd(&g_ccur1[b], NW);
            __syncthreads();
            const int ch = s_chunk;
            if (ch >= ng) break;
            if (loaded != b) {
                for (int i = tid; i < ntap * 512; i += blockDim.x) {
                    const int it = i >> 9, r = i & 511;
                    const int ix = it % nx, iy = (it / nx) % ny, iz = it / (nx * ny);
                    const int kz = zo ? 1 : (iz ? 2 : 0);
                    const int ky = yo ? 1 : (iy ? 2 : 0);
                    const int kx = xo ? 1 : (ix ? 2 : 0);
                    ws4[i] = reinterpret_cast<const float4*>(w1)[((kz * 3 + ky) * 3 + kx) * 512 + r];
                }
                __syncthreads();
                loaded = b;
            }
            const int gi = ch + warp;
            if (gi >= ng) continue;
            const int base = bs + gi * GP;
            const int cnt  = min(GP, bs + bc - base);

            int idj = 0;
            if (lane < GP) {
                idj = g_order[base + ((lane < cnt) ? lane : 0)];
                scow[lane] = __ldg(c4 + idj);
            }
            __syncwarp();
            #pragma unroll
            for (int j = 0; j < GP; j++) {
                const int id = __shfl_sync(0xffffffffu, idj, j);
                const float v = (j < cnt) ? feats[id * CIN + lane] : 0.f;
                unsigned long long p = (unsigned long long)__float_as_uint(v);
                fdw[j * 32 + lane] = p | (p << 32);
            }
            __syncwarp();

            for (int it = 0; it < ntap; it++) {
                const int ix = it % nx, iy = (it / nx) % ny, iz = it / (nx * ny);
                const float4* wt = ws4 + it * 512;
                unsigned long long acc[4][2] = {{0,0},{0,0},{0,0},{0,0}};
                #pragma unroll
                for (int cb = 0; cb < 16; cb++) {
                    const ulonglong2 wA = *reinterpret_cast<const ulonglong2*>(wt + (2 * cb) * 16 + q);
                    const ulonglong2 wB = *reinterpret_cast<const ulonglong2*>(wt + (2 * cb + 1) * 16 + q);
                    #pragma unroll
                    for (int i = 0; i < 4; i++) {
                        const ulonglong2 f = *reinterpret_cast<const ulonglong2*>(fdw + (h + 2 * i) * 32 + 2 * cb);
                        ffma2(acc[i][0], f.x, wA.x); ffma2(acc[i][1], f.x, wA.y);
                        ffma2(acc[i][0], f.y, wB.x); ffma2(acc[i][1], f.y, wB.y);
                    }
                }
                #pragma unroll
                for (int i = 0; i < 4; i++) {
                    const int j = h + 2 * i;
                    if (j < cnt) {
                        const int4 c = scow[j];
                        const int mz = (c.y >> 1) - iz;
                        const int my = (c.z >> 1) - iy;
                        const int mx = (c.w >> 1) - ix;
                        const bool vz = zo || (iz ? (c.y > 0) : (mz < DM));
                        const bool vy = yo || (iy ? (c.z > 0) : (my < HM));
                        const bool vx = xo || (ix ? (c.w > 0) : (mx < WM));
                        if (vz && vy && vx) {
                            float* p = g_mid + ((((c.x * DM + mz) * HM + my) * WM + mx) << 6) + 4 * q;
                            const uint2 a0 = *reinterpret_cast<const uint2*>(&acc[i][0]);
                            const uint2 a1 = *reinterpret_cast<const uint2*>(&acc[i][1]);
                            asm volatile("red.global.add.v4.f32 [%0], {%1,%2,%3,%4};"
                                :: "l"(p),
                                   "f"(__uint_as_float(a0.x)), "f"(__uint_as_float(a0.y)),
                                   "f"(__uint_as_float(a1.x)), "f"(__uint_as_float(a1.y))
                                : "memory");
                        }
                    }
                }
            }
        }
    }
}

// ---------------------------------------------------------------------------
// Phase 3: gather transposed-conv. Same scheduling; lane = ci.
// Weights transposed in smem: [tap][cog][ci] float4 (coalesced LDS.128).
// Mid rows staged per tap (broadcast reads). FFMA2 with final horiz add.
// ---------------------------------------------------------------------------
__global__ void __launch_bounds__(512, 2) gather_deconv(
    const int*   __restrict__ coors,
    const float* __restrict__ w2,
    float*       __restrict__ out) {
    extern __shared__ float sh[];
    float4* ws4 = reinterpret_cast<float4*>(sh);        // [it][cog][ci] float4
    float*  mst = sh + 16384;                           // NW * GP*64 floats
    int4* sco = reinterpret_cast<int4*>(mst + NW * GP * 64);
    __shared__ int s_chunk;

    const int tid  = threadIdx.x;
    const int warp = tid >> 5, lane = tid & 31;
    float* msw = mst + warp * (GP * 64);
    const float4* msw4 = reinterpret_cast<const float4*>(msw);
    int4* scow = sco + warp * GP;
    const int4* c4 = reinterpret_cast<const int4*>(coors);
    const float4* w2_4 = reinterpret_cast<const float4*>(w2);

    int loaded = -1;
    for (int b = 0; b < 8; b++) {
        const int zo = (b >> 2) & 1, yo = (b >> 1) & 1, xo = b & 1;
        const int nx = 2 - xo, ny = 2 - yo, nz = 2 - zo;
        const int ntap = nx * ny * nz;
        const int ng = g_ng[b];
        const int bs = g_bstart[b], bc = g_cntS[b];
        while (true) {
            __syncthreads();
            if (tid == 0) s_chunk = atomicAdd(&g_ccur2[b], NW);
            __syncthreads();
            const int ch = s_chunk;
            if (ch >= ng) break;
            if (loaded != b) {
                for (int i = tid; i < ntap * 512; i += blockDim.x) {
                    const int it = i >> 9, cog = (i >> 5) & 15, ci = i & 31;
                    const int ix = it % nx, iy = (it / nx) % ny, iz = it / (nx * ny);
                    const int kz = zo ? 1 : (iz ? 2 : 0);
                    const int ky = yo ? 1 : (iy ? 2 : 0);
                    const int kx = xo ? 1 : (ix ? 2 : 0);
                    ws4[i] = w2_4[(((kz * 3 + ky) * 3 + kx) * 32 + ci) * 16 + cog];
                }
                __syncthreads();
                loaded = b;
            }
            const int gi = ch + warp;
            if (gi >= ng) continue;
            const int base = bs + gi * GP;
            const int cnt  = min(GP, bs + bc - base);

            int4 cj = make_int4(0, 0, 0, 0);
            if (lane < GP) {
                const int id = g_order[base + ((lane < cnt) ? lane : 0)];
                cj = __ldg(c4 + id);
                scow[lane] = cj;
            }
            __syncwarp();

            unsigned long long acc[GP] = {0, 0, 0, 0, 0, 0, 0, 0};
            for (int it = 0; it < ntap; it++) {
                const int ix = it % nx, iy = (it / nx) % ny, iz = it / (nx * ny);
                int mbj = -1;
                if (lane < cnt) {
                    const int mz = (cj.y >> 1) - iz;
                    const int my = (cj.z >> 1) - iy;
                    const int mx = (cj.w >> 1) - ix;
                    const bool vz = zo || (iz ? (cj.y > 0) : (mz < DM));
                    const bool vy = yo || (iy ? (cj.z > 0) : (my < HM));
                    const bool vx = xo || (ix ? (cj.w > 0) : (mx < WM));
                    if (vz && vy && vx)
                        mbj = (((cj.x * DM + mz) * HM + my) * WM + mx) << 6;
                }
                __syncwarp();
                #pragma unroll
                for (int j = 0; j < GP; j++) {
                    const int mb = __shfl_sync(0xffffffffu, mbj, j);
                    msw[j * 64 + lane]      = (mb >= 0) ? g_mid[mb + lane]      : 0.f;
                    msw[j * 64 + 32 + lane] = (mb >= 0) ? g_mid[mb + 32 + lane] : 0.f;
                }
                __syncwarp();
                const float4* wt = ws4 + it * 512;
                for (int cog = 0; cog < 16; cog++) {
                    const ulonglong2 w = *reinterpret_cast<const ulonglong2*>(wt + cog * 32 + lane);
                    #pragma unroll
                    for (int j = 0; j < GP; j++) {
                        const ulonglong2 m = *reinterpret_cast<const ulonglong2*>(msw4 + j * 16 + cog);
                        ffma2(acc[j], m.x, w.x);
                        ffma2(acc[j], m.y, w.y);
                    }
                }
            }

            for (int j = 0; j < cnt; j++) {
                const int4 c = scow[j];
                const uint2 a = *reinterpret_cast<const uint2*>(&acc[j]);
                const float r = __uint_as_float(a.x) + __uint_as_float(a.y);
                long o = (long)(c.x * CIN + lane) * DD + c.y;
                o = o * HH + c.z;
                o = o * WW + c.w;
                out[o] = r;
            }
        }
    }
}

// ---------------------------------------------------------------------------
// Launcher
// ---------------------------------------------------------------------------
extern "C" void kernel_launch(void* const* d_in, const int* in_sizes, int n_in,
                              void* d_out, int /*out_size*/) {
    const float* feats = nullptr;
    const int*   coors = nullptr;
    const float* w1 = nullptr;
    const float* w2 = nullptr;
    for (int i = 0; i < n_in; i++) {
        if      (in_sizes[i] == NPTS * CIN) feats = (const float*)d_in[i];
        else if (in_sizes[i] == NPTS * 4)   coors = (const int*)d_in[i];
        else if (in_sizes[i] == WSZ) {
            if (!w1) w1 = (const float*)d_in[i];
            else     w2 = (const float*)d_in[i];
        }
    }
    if (!feats || !coors || !w1 || !w2) return;

    int nsm = 148;
    cudaDeviceGetAttribute(&nsm, cudaDevAttrMultiProcessorCount, 0);

    // smem: weights 64KB + staging 32KB + coords 2KB = 100,352 B each
    const int smem1 = 16384 * 4 + NW * GP * 32 * 8 + NW * GP * 16;
    const int smem3 = 16384 * 4 + NW * GP * 64 * 4 + NW * GP * 16;
    cudaFuncSetAttribute(scatter_conv,  cudaFuncAttributeMaxDynamicSharedMemorySize, smem1);
    cudaFuncSetAttribute(gather_deconv, cudaFuncAttributeMaxDynamicSharedMemorySize, smem3);

    zero_hist<<<2048, 256>>>(reinterpret_cast<float4*>(d_out), coors);
    scan_kernel<<<1, 1>>>();
    scatter_idx_kernel<<<(NPTS + 255) / 256, 256>>>(coors);
    scatter_conv<<<2 * nsm, 512, smem1>>>(feats, coors, w1);
    gather_deconv<<<2 * nsm, 512, smem3>>>(coors, w2, reinterpret_cast<float*>(d_out));
}